// round 7
// baseline (speedup 1.0000x reference)
#include <cuda_runtime.h>
#include <cuda_bf16.h>

// PositionEncoding: out[b,s,:] = is_class ? E_class[class_id] : sincos(v * 2^i * pi)
// B=64, S=8192, 32 levels (E=64), CLASS_NUM=4096.
//
// R6 = R4 core (UNROLL=4, 16 threads/token -> perfect 512B warp stores;
// vectorized scalar loads; one __sincosf + double-angle for the odd level) with
// hygiene fixes:
//  - default write-back stores (no __stcs): output is L2-resident across graph
//    replays (measured DRAM flow << store volume); evict-first was forcing
//    early DRAM writebacks.
//  - unconditional sincos compute + SEL select; ONLY the E_class gather is
//    predicated (@P LDG, no BSSY/BSYNC divergence per unroll step).
//  - block=512, exact grid, no bounds guard.
//
// Angle math (FP64-free "turns"): angle for level i is exactly 2^i * a0 with
// a0 = fl32(v*pi_f) (pow2 scaling commutes with fp32 rounding). u =
// frac(a0*(1/2pi)*2^i) via two-float 1/2pi (~47 bits); pow2 scale and frac
// exact in fp32 -> angle err ~2.4e-5 rad (x2 after one doubling) << 1e-3 tol.

#define NTOK   (64 * 8192)     // 524288 tokens
#define UNROLL 4               // tokens per thread

__global__ __launch_bounds__(512)
void pos_enc_kernel(const float4* __restrict__ values4,    // [NTOK/4]
                    const float4* __restrict__ E_class,    // [4096][16] float4
                    const int4*  __restrict__ class_ids4,  // [NTOK/4]
                    const int4*  __restrict__ is_class4,   // [NTOK/4]
                    float4* __restrict__ out)               // [NTOK][16] float4
{
    unsigned gid  = blockIdx.x * 512u + threadIdx.x;
    unsigned t    = gid & 15u;          // float4 slot -> levels 2t, 2t+1
    unsigned grp  = gid >> 4;           // token group (4 tokens)
    unsigned tok0 = grp * UNROLL;

    // two-float 1/(2pi): C_HI + C_LO ~ 47 bits (folded at compile time)
    constexpr double INV2PI_D = 0.15915494309189533577;
    constexpr float  C_HI = (float)INV2PI_D;
    constexpr float  C_LO = (float)(INV2PI_D - (double)C_HI);
    const float PI_F     = 3.14159265358979323846f;   // rounds to pi_f32
    const float TWO_PI_F = 6.28318530717958647693f;

    // 2^(2t) as exact fp32 via exponent bits
    float scale_e = __uint_as_float((127u + 2u * t) << 23);

    // ---- 3 vector loads cover all 12 per-token scalars ----
    float4 v4 = __ldg(&values4[grp]);
    int4   c4 = __ldg(&class_ids4[grp]);
    int4   m4 = __ldg(&is_class4[grp]);

    float v[UNROLL]  = { v4.x, v4.y, v4.z, v4.w };
    int   cid[UNROLL]= { c4.x, c4.y, c4.z, c4.w };
    int   ic[UNROLL] = { m4.x, m4.y, m4.z, m4.w };

    // ---- predicated E_class gathers, issued early (@P LDG, no branch) ----
    float4 cls[UNROLL];
#pragma unroll
    for (int j = 0; j < UNROLL; j++) {
        if (ic[j] == 1)
            cls[j] = __ldg(&E_class[(unsigned)cid[j] * 16u + t]);
    }

    // ---- unconditional compute, SEL select, write-back store ----
#pragma unroll
    for (int j = 0; j < UNROLL; j++) {
        float a0   = v[j] * PI_F;                 // fl32(v*pi) — matches reference
        float s_hi = a0 * C_HI;
        float perr = fmaf(a0, C_HI, -s_hi);       // exact residual of a0*C_HI
        float s_lo = fmaf(a0, C_LO, perr);        // two-float tail, ~47 bits total
        float y_hi = s_hi * scale_e;              // exact (pow2 scale)
        float y_lo = s_lo * scale_e;              // exact
        float f    = (y_hi - floorf(y_hi)) + (y_lo - floorf(y_lo)); // exact fracs
        float w0   = f - rintf(f);                // turn in [-0.5, 0.5]

        float s0, c0;
        __sincosf(w0 * TWO_PI_F, &s0, &c0);       // level 2t
        float s1 = 2.0f * s0 * c0;                // level 2t+1 via double angle
        float c1 = fmaf(-2.0f * s0, s0, 1.0f);

        bool  is_cls = (ic[j] == 1);
        float4 o;
        o.x = is_cls ? cls[j].x : s0;
        o.y = is_cls ? cls[j].y : c0;
        o.z = is_cls ? cls[j].z : s1;
        o.w = is_cls ? cls[j].w : c1;
        out[(tok0 + j) * 16u + t] = o;            // default write-back (L2-resident)
    }
}

extern "C" void kernel_launch(void* const* d_in, const int* in_sizes, int n_in,
                              void* d_out, int out_size)
{
    const float4* values4    = (const float4*)d_in[0];
    const float4* E_class    = (const float4*)d_in[1];
    const int4*   class_ids4 = (const int4*)d_in[2];
    const int4*   is_class4  = (const int4*)d_in[3];
    float4*       out        = (float4*)d_out;

    const int threads = 512;
    const int total   = (NTOK / UNROLL) * 16;     // 2,097,152 threads
    const int blocks  = total / threads;          // 4096, exact
    pos_enc_kernel<<<blocks, threads>>>(values4, E_class, class_ids4, is_class4, out);
}

// round 8
// speedup vs baseline: 1.1620x; 1.1620x over previous
#include <cuda_runtime.h>
#include <cuda_bf16.h>

// PositionEncoding: out[b,s,:] = is_class ? E_class[class_id] : sincos(v * 2^i * pi)
// B=64, S=8192, 32 levels (E=64), CLASS_NUM=4096.
//
// R7 = R4 (best: 22.98us) + ONE change: branchless compute loop.
//   - R4 kept: UNROLL=4, block=256, 16 threads/token (perfect 512B warp
//     stores), vectorized scalar loads, __stcs streaming stores (load-bearing
//     for back-to-back graph replays: evict-first drains dirty output lines
//     eagerly instead of stalling next replay's store allocations), single
//     __sincosf + double-angle.
//   - changed: compute is unconditional, result merged with FSEL; only the
//     E_class gather is predicated (@P LDG). Removes 4 BSSY/BSYNC pairs per
//     thread (~75% of unroll steps diverged with 2 tokens per warp).
//
// Angle math (FP64-free "turns"): angle for level i is exactly 2^i * a0 with
// a0 = fl32(v*pi_f) (pow2 scaling commutes with fp32 rounding). u =
// frac(a0*(1/2pi)*2^i) via two-float 1/2pi (~47 bits); pow2 scale and frac
// exact in fp32 -> angle err ~2.4e-5 rad (x2 after one doubling) << 1e-3 tol.

#define NTOK   (64 * 8192)     // 524288 tokens
#define UNROLL 4               // tokens per thread

__global__ __launch_bounds__(256)
void pos_enc_kernel(const float4* __restrict__ values4,    // [NTOK/4]
                    const float4* __restrict__ E_class,    // [4096][16] float4
                    const int4*  __restrict__ class_ids4,  // [NTOK/4]
                    const int4*  __restrict__ is_class4,   // [NTOK/4]
                    float4* __restrict__ out)               // [NTOK][16] float4
{
    unsigned gid  = blockIdx.x * 256u + threadIdx.x;
    unsigned t    = gid & 15u;          // float4 slot -> levels 2t, 2t+1
    unsigned grp  = gid >> 4;           // token group (4 tokens)
    unsigned tok0 = grp * UNROLL;

    // two-float 1/(2pi): C_HI + C_LO ~ 47 bits (folded at compile time)
    constexpr double INV2PI_D = 0.15915494309189533577;
    constexpr float  C_HI = (float)INV2PI_D;
    constexpr float  C_LO = (float)(INV2PI_D - (double)C_HI);
    const float PI_F     = 3.14159265358979323846f;   // rounds to pi_f32
    const float TWO_PI_F = 6.28318530717958647693f;

    // 2^(2t) as exact fp32 via exponent bits
    float scale_e = __uint_as_float((127u + 2u * t) << 23);

    // ---- 3 vector loads cover all 12 per-token scalars ----
    float4 v4 = __ldg(&values4[grp]);
    int4   c4 = __ldg(&class_ids4[grp]);
    int4   m4 = __ldg(&is_class4[grp]);

    float v[UNROLL]  = { v4.x, v4.y, v4.z, v4.w };
    int   cid[UNROLL]= { c4.x, c4.y, c4.z, c4.w };
    int   ic[UNROLL] = { m4.x, m4.y, m4.z, m4.w };

    // ---- predicated E_class gathers, issued early (@P LDG, no branch) ----
    float4 cls[UNROLL];
#pragma unroll
    for (int j = 0; j < UNROLL; j++) {
        if (ic[j] == 1)
            cls[j] = __ldg(&E_class[(unsigned)cid[j] * 16u + t]);
    }

    // ---- unconditional compute, FSEL merge, streaming store ----
#pragma unroll
    for (int j = 0; j < UNROLL; j++) {
        float a0   = v[j] * PI_F;                 // fl32(v*pi) — matches reference
        float s_hi = a0 * C_HI;
        float perr = fmaf(a0, C_HI, -s_hi);       // exact residual of a0*C_HI
        float s_lo = fmaf(a0, C_LO, perr);        // two-float tail, ~47 bits total
        float y_hi = s_hi * scale_e;              // exact (pow2 scale)
        float y_lo = s_lo * scale_e;              // exact
        float f    = (y_hi - floorf(y_hi)) + (y_lo - floorf(y_lo)); // exact fracs
        float w0   = f - rintf(f);                // turn in [-0.5, 0.5]

        float s0, c0;
        __sincosf(w0 * TWO_PI_F, &s0, &c0);       // level 2t
        float s1 = 2.0f * s0 * c0;                // level 2t+1 via double angle
        float c1 = fmaf(-2.0f * s0, s0, 1.0f);

        bool is_cls = (ic[j] == 1);
        float4 o;
        o.x = is_cls ? cls[j].x : s0;
        o.y = is_cls ? cls[j].y : c0;
        o.z = is_cls ? cls[j].z : s1;
        o.w = is_cls ? cls[j].w : c1;
        __stcs(&out[(tok0 + j) * 16u + t], o);    // evict-first: never re-read
    }
}

extern "C" void kernel_launch(void* const* d_in, const int* in_sizes, int n_in,
                              void* d_out, int out_size)
{
    const float4* values4    = (const float4*)d_in[0];
    const float4* E_class    = (const float4*)d_in[1];
    const int4*   class_ids4 = (const int4*)d_in[2];
    const int4*   is_class4  = (const int4*)d_in[3];
    float4*       out        = (float4*)d_out;

    const int threads = 256;
    const int total   = (NTOK / UNROLL) * 16;     // 2,097,152 threads
    const int blocks  = total / threads;          // 8192, exact
    pos_enc_kernel<<<blocks, threads>>>(values4, E_class, class_ids4, is_class4, out);
}

// round 9
// speedup vs baseline: 1.2361x; 1.0638x over previous
#include <cuda_runtime.h>
#include <cuda_bf16.h>

// PositionEncoding: out[b,s,:] = is_class ? E_class[class_id] : sincos(v * 2^i * pi)
// B=64, S=8192, 32 levels (E=64), CLASS_NUM=4096.
//
// R8 = R4 memory shape (UNROLL=4, block=256, 16 threads/token -> perfect 512B
// warp stores; vectorized scalar loads; __stcs streaming stores) with the
// branch/select overhead removed at ZERO register cost:
//   compute sincos into the output registers unconditionally, then a
//   predicated @P LDG.128 overwrites those same registers for class tokens,
//   then store. No cls[] staging (R7's mistake: regs 40 -> occ 62%), no FSEL,
//   no BSSY/BSYNC. __launch_bounds__(256,8) pins regs<=32 so occ stays ~85%
//   (wall time under graph replay tracks occupancy; see R5-R7 post-mortems).
//
// Angle math (FP64-free "turns"): angle for level i is exactly 2^i * a0 with
// a0 = fl32(v*pi_f) (pow2 scaling commutes with fp32 rounding). u =
// frac(a0*(1/2pi)*2^i) via two-float 1/2pi (~47 bits); pow2 scale and frac
// exact in fp32 -> angle err ~2.4e-5 rad (x2 after one doubling) << 1e-3 tol.

#define NTOK   (64 * 8192)     // 524288 tokens
#define UNROLL 4               // tokens per thread

__global__ __launch_bounds__(256, 8)
void pos_enc_kernel(const float4* __restrict__ values4,    // [NTOK/4]
                    const float4* __restrict__ E_class,    // [4096][16] float4
                    const int4*  __restrict__ class_ids4,  // [NTOK/4]
                    const int4*  __restrict__ is_class4,   // [NTOK/4]
                    float4* __restrict__ out)               // [NTOK][16] float4
{
    unsigned gid  = blockIdx.x * 256u + threadIdx.x;
    unsigned t    = gid & 15u;          // float4 slot -> levels 2t, 2t+1
    unsigned grp  = gid >> 4;           // token group (4 tokens)
    unsigned tok0 = grp * UNROLL;

    // two-float 1/(2pi): C_HI + C_LO ~ 47 bits (folded at compile time)
    constexpr double INV2PI_D = 0.15915494309189533577;
    constexpr float  C_HI = (float)INV2PI_D;
    constexpr float  C_LO = (float)(INV2PI_D - (double)C_HI);
    const float PI_F     = 3.14159265358979323846f;   // rounds to pi_f32
    const float TWO_PI_F = 6.28318530717958647693f;

    // 2^(2t) as exact fp32 via exponent bits
    float scale_e = __uint_as_float((127u + 2u * t) << 23);

    // ---- 3 vector loads cover all 12 per-token scalars ----
    float4 v4 = __ldg(&values4[grp]);
    int4   c4 = __ldg(&class_ids4[grp]);
    int4   m4 = __ldg(&is_class4[grp]);

    float v[UNROLL]  = { v4.x, v4.y, v4.z, v4.w };
    int   cid[UNROLL]= { c4.x, c4.y, c4.z, c4.w };
    int   ic[UNROLL] = { m4.x, m4.y, m4.z, m4.w };

    // ---- compute all slots into output regs (unconditional, no staging) ----
    float4 o[UNROLL];
#pragma unroll
    for (int j = 0; j < UNROLL; j++) {
        float a0   = v[j] * PI_F;                 // fl32(v*pi) — matches reference
        float s_hi = a0 * C_HI;
        float perr = fmaf(a0, C_HI, -s_hi);       // exact residual of a0*C_HI
        float s_lo = fmaf(a0, C_LO, perr);        // two-float tail, ~47 bits total
        float y_hi = s_hi * scale_e;              // exact (pow2 scale)
        float y_lo = s_lo * scale_e;              // exact
        float f    = (y_hi - floorf(y_hi)) + (y_lo - floorf(y_lo)); // exact fracs
        float w0   = f - rintf(f);                // turn in [-0.5, 0.5]

        float s0, c0;
        __sincosf(w0 * TWO_PI_F, &s0, &c0);       // level 2t
        float s1 = 2.0f * s0 * c0;                // level 2t+1 via double angle
        float c1 = fmaf(-2.0f * s0, s0, 1.0f);
        o[j] = make_float4(s0, c0, s1, c1);
    }

    // ---- predicated gathers overwrite the SAME registers (@P LDG.128) ----
#pragma unroll
    for (int j = 0; j < UNROLL; j++) {
        if (ic[j] == 1)
            o[j] = __ldg(&E_class[(unsigned)cid[j] * 16u + t]);
    }

    // ---- streaming stores ----
#pragma unroll
    for (int j = 0; j < UNROLL; j++)
        __stcs(&out[(tok0 + j) * 16u + t], o[j]); // evict-first: never re-read

}

extern "C" void kernel_launch(void* const* d_in, const int* in_sizes, int n_in,
                              void* d_out, int out_size)
{
    const float4* values4    = (const float4*)d_in[0];
    const float4* E_class    = (const float4*)d_in[1];
    const int4*   class_ids4 = (const int4*)d_in[2];
    const int4*   is_class4  = (const int4*)d_in[3];
    float4*       out        = (float4*)d_out;

    const int threads = 256;
    const int total   = (NTOK / UNROLL) * 16;     // 2,097,152 threads
    const int blocks  = total / threads;          // 8192, exact
    pos_enc_kernel<<<blocks, threads>>>(values4, E_class, class_ids4, is_class4, out);
}